// round 1
// baseline (speedup 1.0000x reference)
#include <cuda_runtime.h>
#include <math.h>

#define BATCH   65536
#define NUMC    512
#define DIM     256
#define D4      64            // DIM/4
#define BM      128
#define BN      64
#define NTILES  (NUMC/BN)     // 8
#define THREADS 512
#define NBLOCKS (BATCH/BM)    // 512
#define ALPHA   0.05f

__device__ float g_csq[NUMC];
__device__ float g_partials[NBLOCKS];

typedef unsigned long long ull;

__device__ __forceinline__ void fma2(ull& acc, ull a, ull b) {
    asm("fma.rn.f32x2 %0, %1, %2, %0;" : "+l"(acc) : "l"(a), "l"(b));
}

// ---------------------------------------------------------------------------
// Kernel 0: per-center squared norms. One warp per center, coalesced.
// ---------------------------------------------------------------------------
__global__ void csq_kernel(const float* __restrict__ centers) {
    int w    = blockIdx.x * (blockDim.x >> 5) + (threadIdx.x >> 5);
    int lane = threadIdx.x & 31;
    const float* row = centers + w * DIM;
    float s = 0.f;
    #pragma unroll
    for (int i = 0; i < DIM / 32; i++) {
        float v = row[lane + i * 32];
        s += v * v;
    }
    #pragma unroll
    for (int off = 16; off; off >>= 1)
        s += __shfl_xor_sync(0xffffffffu, s, off);
    if (lane == 0) g_csq[w] = s;
}

// ---------------------------------------------------------------------------
// Kernel 1: main tiled "GEMM + row-min" kernel.
// Block tile: 128 rows x 64 centers/iter (x8 iters = all 512 centers).
// A tile persistent in smem (128 KB), B tile per-iter (64 KB).
// Per-thread 4x4 micro-tile with packed f32x2 FMA accumulators.
// XOR swizzle on smem chunks for conflict-minimal LDS.128.
// ---------------------------------------------------------------------------
extern __shared__ char smem[];

__global__ void __launch_bounds__(THREADS, 1)
kmeans_main(const float* __restrict__ emb, const float* __restrict__ cen) {
    float4* As4   = (float4*)smem;                         // BM * D4 float4
    float4* Bs4   = (float4*)(smem + (size_t)BM * DIM * 4);// BN * D4 float4
    float*  csq_s = (float*)(smem + (size_t)(BM + BN) * DIM * 4);
    float*  red   = csq_s + BN;                            // 16 floats

    const int tid  = threadIdx.x;
    const int tidm = tid >> 4;       // 0..31  (row group)
    const int tidn = tid & 15;       // 0..15  (center group)
    const int m0   = tidm * 4;
    const int row0 = blockIdx.x * BM;
    const int swA0 = (tidm & 3) * 4; // (m0 & 15), low 2 bits zero

    // ---- Load A tile once (coalesced gmem, swizzled smem store) ----
    const float4* e4 = (const float4*)emb;
    #pragma unroll
    for (int s = 0; s < (BM * D4) / THREADS; s++) {   // 16
        int idx = tid + s * THREADS;
        int r = idx >> 6, c = idx & 63;
        As4[r * D4 + (c ^ (r & 15))] = e4[(size_t)(row0 + r) * D4 + c];
    }

    float minv[4];
    #pragma unroll
    for (int i = 0; i < 4; i++) minv[i] = 3.402823466e38f;

    const ulonglong2* Au = (const ulonglong2*)As4;
    const ulonglong2* Bu = (const ulonglong2*)Bs4;
    const float4*     c4 = (const float4*)cen;

    for (int t = 0; t < NTILES; t++) {
        __syncthreads();   // previous compute done before overwriting Bs
        const int cen0 = t * BN;
        #pragma unroll
        for (int s = 0; s < (BN * D4) / THREADS; s++) {  // 8
            int idx = tid + s * THREADS;
            int n = idx >> 6, c = idx & 63;
            Bs4[n * D4 + (c ^ ((n >> 2) & 15))] = c4[(size_t)(cen0 + n) * D4 + c];
        }
        if (tid < BN) csq_s[tid] = g_csq[cen0 + tid];
        __syncthreads();

        ull acc[4][4];
        #pragma unroll
        for (int i = 0; i < 4; i++)
            #pragma unroll
            for (int j = 0; j < 4; j++) acc[i][j] = 0ull;

        #pragma unroll 8
        for (int kk = 0; kk < D4; kk++) {
            const int ca = kk ^ swA0;
            const int cb = kk ^ tidn;
            ulonglong2 av[4], bv[4];
            #pragma unroll
            for (int i = 0; i < 4; i++)
                av[i] = Au[(m0 + i) * D4 + (ca ^ i)];
            #pragma unroll
            for (int j = 0; j < 4; j++)
                bv[j] = Bu[(tidn * 4 + j) * D4 + cb];
            #pragma unroll
            for (int i = 0; i < 4; i++)
                #pragma unroll
                for (int j = 0; j < 4; j++) {
                    fma2(acc[i][j], av[i].x, bv[j].x);
                    fma2(acc[i][j], av[i].y, bv[j].y);
                }
        }

        // epilogue per tile: min of (||c||^2 - 2 x.c)
        #pragma unroll
        for (int i = 0; i < 4; i++)
            #pragma unroll
            for (int j = 0; j < 4; j++) {
                float lo, hi;
                asm("mov.b64 {%0,%1}, %2;" : "=f"(lo), "=f"(hi) : "l"(acc[i][j]));
                float dot  = lo + hi;
                float cand = csq_s[tidn * 4 + j] - 2.0f * dot;
                minv[i] = fminf(minv[i], cand);
            }
    }

    // ---- x_sq partials from resident A tile (deterministic, no atomics) ----
    float xp[4] = {0.f, 0.f, 0.f, 0.f};
    #pragma unroll
    for (int s = 0; s < 4; s++) {
        int cc = tidn + s * 16;
        #pragma unroll
        for (int i = 0; i < 4; i++) {
            float4 v = As4[(m0 + i) * D4 + (cc ^ (swA0 | i))];
            xp[i] += v.x * v.x + v.y * v.y + v.z * v.z + v.w * v.w;
        }
    }

    // ---- reduce across the 16 lanes sharing the same 4 rows ----
    #pragma unroll
    for (int off = 8; off; off >>= 1) {
        #pragma unroll
        for (int i = 0; i < 4; i++) {
            minv[i] = fminf(minv[i], __shfl_xor_sync(0xffffffffu, minv[i], off, 16));
            xp[i]  +=                __shfl_xor_sync(0xffffffffu, xp[i],  off, 16);
        }
    }

    float local = 0.f;
    if (tidn == 0) {
        #pragma unroll
        for (int i = 0; i < 4; i++)
            local += sqrtf(fmaxf(xp[i] + minv[i], 0.f));
    }
    // combine lane 0 and lane 16 of each warp
    local += __shfl_down_sync(0xffffffffu, local, 16);

    const int warp = tid >> 5, lane = tid & 31;
    if (lane == 0) red[warp] = local;
    __syncthreads();
    if (warp == 0) {
        float v = (lane < 16) ? red[lane] : 0.f;
        #pragma unroll
        for (int off = 8; off; off >>= 1)
            v += __shfl_down_sync(0xffffffffu, v, off);
        if (lane == 0) g_partials[blockIdx.x] = v;
    }
}

// ---------------------------------------------------------------------------
// Kernel 2: deterministic tree reduce of 512 block partials -> scalar.
// ---------------------------------------------------------------------------
__global__ void finalize_kernel(float* __restrict__ out) {
    __shared__ float s[THREADS];
    int tid = threadIdx.x;
    s[tid] = g_partials[tid];   // NBLOCKS == THREADS == 512
    __syncthreads();
    #pragma unroll
    for (int off = 256; off; off >>= 1) {
        if (tid < off) s[tid] += s[tid + off];
        __syncthreads();
    }
    if (tid == 0) out[0] = s[0] * (ALPHA / (float)BATCH);
}

// ---------------------------------------------------------------------------
extern "C" void kernel_launch(void* const* d_in, const int* in_sizes, int n_in,
                              void* d_out, int out_size) {
    const float* emb;
    const float* cen;
    if (in_sizes[0] == BATCH * DIM) {
        emb = (const float*)d_in[0];
        cen = (const float*)d_in[1];
    } else {
        emb = (const float*)d_in[1];
        cen = (const float*)d_in[0];
    }
    float* out = (float*)d_out;

    const int smem_bytes = (BM + BN) * DIM * 4 + BN * 4 + 16 * 4;
    cudaFuncSetAttribute(kmeans_main,
                         cudaFuncAttributeMaxDynamicSharedMemorySize, smem_bytes);

    csq_kernel<<<NUMC / 8, 256>>>(cen);
    kmeans_main<<<NBLOCKS, THREADS, smem_bytes>>>(emb, cen);
    finalize_kernel<<<1, THREADS>>>(out);
}

// round 3
// speedup vs baseline: 5.9522x; 5.9522x over previous
#include <cuda_runtime.h>
#include <cuda_bf16.h>
#include <cstdint>
#include <math.h>

#define BATCH   65536
#define NUMC    512
#define DIM     256
#define BM      128
#define BN      128
#define NT      (NUMC/BN)      // 4
#define THREADS 256
#define NBLOCKS (BATCH/BM)     // 512
#define ALPHA   0.05f
#define FINF    3.402823466e38f

// smem byte offsets
#define SAS     0              // A tile bf16 128x256 swizzled       (65536)
#define SB0     65536          // B buf 0                            (65536)
#define SB1     131072         // B buf 1                            (65536)
#define SCSQ    196608         // 512 f                              (2048)
#define SXSQ    198656         // 128 f                              (512)
#define SMINB   199168         // 128x2 f                            (1024)
#define SRED    200192         // 4 f + pad                          (64)
#define SMEM_TOTAL 200256

__device__ float g_csq[NUMC];
__device__ __align__(16) uint32_t g_cenB[NUMC * DIM / 2];  // bf16x2, [n][k]
__device__ float g_partials[NBLOCKS];

// ---------------- helpers ----------------
__device__ __forceinline__ uint32_t smem_u32(const void* p) {
    uint32_t a;
    asm("{ .reg .u64 t; cvta.to.shared.u64 t, %1; cvt.u32.u64 %0, t; }"
        : "=r"(a) : "l"(p));
    return a;
}
__device__ __forceinline__ uint32_t bf16pair(float lo, float hi) {
    uint32_t r;
    asm("cvt.rn.satfinite.bf16x2.f32 %0, %1, %2;" : "=r"(r) : "f"(hi), "f"(lo));
    return r;
}
__device__ __forceinline__ void mma16816(float c[4], const uint32_t a[4],
                                         uint32_t b0, uint32_t b1) {
    asm volatile(
        "mma.sync.aligned.m16n8k16.row.col.f32.bf16.bf16.f32 "
        "{%0,%1,%2,%3}, {%4,%5,%6,%7}, {%8,%9}, {%0,%1,%2,%3};"
        : "+f"(c[0]), "+f"(c[1]), "+f"(c[2]), "+f"(c[3])
        : "r"(a[0]), "r"(a[1]), "r"(a[2]), "r"(a[3]), "r"(b0), "r"(b1));
}
#define CP_ASYNC16(dst, src) \
    asm volatile("cp.async.cg.shared.global [%0], [%1], 16;" :: "r"(dst), "l"(src))
#define CP_COMMIT()  asm volatile("cp.async.commit_group;" ::: "memory")
#define CP_WAIT0()   asm volatile("cp.async.wait_group 0;" ::: "memory")

// ---------------------------------------------------------------------------
// Kernel 0: center norms (exact fp32) + bf16 copy of centers, [n][k] layout.
// One warp per center.
// ---------------------------------------------------------------------------
__global__ void prep_kernel(const float* __restrict__ cen) {
    int w    = blockIdx.x * 8 + (threadIdx.x >> 5);
    int lane = threadIdx.x & 31;
    const float2* row = (const float2*)(cen + (size_t)w * DIM);
    float s = 0.f;
    #pragma unroll
    for (int i = 0; i < 4; i++) {
        float2 v = row[lane + 32 * i];
        s += v.x * v.x + v.y * v.y;
        g_cenB[w * (DIM / 2) + lane + 32 * i] = bf16pair(v.x, v.y);
    }
    #pragma unroll
    for (int off = 16; off; off >>= 1)
        s += __shfl_xor_sync(0xffffffffu, s, off);
    if (lane == 0) g_csq[w] = s;
}

// ---------------------------------------------------------------------------
// Kernel 1: bf16 mma.sync GEMM (128x512x256 per block) fused with row-min,
// sqrt, and deterministic block reduction.
// ---------------------------------------------------------------------------
extern __shared__ char smem[];

__device__ __forceinline__ void cp_tile(uint32_t sb_dst, int t, int tid) {
    const char* src = (const char*)g_cenB + (size_t)t * BN * 512;
    #pragma unroll
    for (int s = 0; s < 16; s++) {
        int idx = tid + s * THREADS;
        int n = idx >> 5, c16 = idx & 31;
        uint32_t dst = sb_dst + n * 512 + (uint32_t)((c16 ^ (n & 7)) << 4);
        CP_ASYNC16(dst, src + n * 512 + c16 * 16);
    }
    CP_COMMIT();
}

__global__ void __launch_bounds__(THREADS, 1)
kmeans_main(const float* __restrict__ emb) {
    const uint32_t sb = smem_u32(smem);
    const int tid   = threadIdx.x;
    const int w     = tid >> 5, lane = tid & 31;
    const int g     = lane >> 2, tig = lane & 3;
    const int warpM = w >> 1, warpN = w & 1;
    const int m0    = warpM * 32;
    const uint32_t g16 = (uint32_t)g << 4;

    // kick off B tile 0 first (overlaps the A prologue)
    cp_tile(sb + SB0, 0, tid);

    // ---- A load: 2 threads per row, convert to bf16, swizzled store, xsq ----
    {
        int row = tid >> 1, half = tid & 1;
        const float4* src = (const float4*)emb
                          + (size_t)(blockIdx.x * BM + row) * (DIM / 4) + half * 32;
        char* dstrow = smem + SAS + row * 512;
        const int key = row & 7;
        float xs = 0.f;
        #pragma unroll
        for (int j = 0; j < 32; j++) {
            float4 v = src[j];
            xs += v.x * v.x + v.y * v.y + v.z * v.z + v.w * v.w;
            int c4 = half * 32 + j;
            uint2 pk;
            pk.x = bf16pair(v.x, v.y);
            pk.y = bf16pair(v.z, v.w);
            *(uint2*)(dstrow + (((c4 >> 1) ^ key) << 4) + ((c4 & 1) << 3)) = pk;
        }
        xs += __shfl_xor_sync(0xffffffffu, xs, 1);
        if (!half) ((float*)(smem + SXSQ))[row] = xs;
    }
    ((float*)(smem + SCSQ))[tid]       = g_csq[tid];
    ((float*)(smem + SCSQ))[tid + 256] = g_csq[tid + 256];

    CP_WAIT0();
    __syncthreads();

    // ---- per-thread fragment base addresses ----
    const char* aP[2][2];
    #pragma unroll
    for (int mi = 0; mi < 2; mi++)
        #pragma unroll
        for (int h = 0; h < 2; h++)
            aP[mi][h] = smem + SAS + (m0 + mi * 16 + g + 8 * h) * 512 + 4 * tig;
    uint32_t bOff[8];
    #pragma unroll
    for (int nj = 0; nj < 8; nj++)
        bOff[nj] = (uint32_t)((warpN * 64 + nj * 8 + g) * 512 + 4 * tig);

    const float* csq_s = (const float*)(smem + SCSQ);
    float rm[2][2] = {{FINF, FINF}, {FINF, FINF}};

    for (int t = 0; t < NT; t++) {
        if (t + 1 < NT)
            cp_tile(sb + (((t + 1) & 1) ? SB1 : SB0), t + 1, tid);
        const char* B = smem + ((t & 1) ? SB1 : SB0);

        float c[2][8][4];
        #pragma unroll
        for (int mi = 0; mi < 2; mi++)
            #pragma unroll
            for (int nj = 0; nj < 8; nj++)
                #pragma unroll
                for (int q = 0; q < 4; q++) c[mi][nj][q] = 0.f;

        #pragma unroll
        for (int ks = 0; ks < 16; ks++) {
            const uint32_t ka = ((uint32_t)ks << 5) ^ g16;
            const uint32_t kb = ka ^ 16u;
            uint32_t a[2][4];
            #pragma unroll
            for (int mi = 0; mi < 2; mi++) {
                a[mi][0] = *(const uint32_t*)(aP[mi][0] + ka);
                a[mi][1] = *(const uint32_t*)(aP[mi][1] + ka);
                a[mi][2] = *(const uint32_t*)(aP[mi][0] + kb);
                a[mi][3] = *(const uint32_t*)(aP[mi][1] + kb);
            }
            #pragma unroll
            for (int nj = 0; nj < 8; nj++) {
                uint32_t b0 = *(const uint32_t*)(B + bOff[nj] + ka);
                uint32_t b1 = *(const uint32_t*)(B + bOff[nj] + kb);
                mma16816(c[0][nj], a[0], b0, b1);
                mma16816(c[1][nj], a[1], b0, b1);
            }
        }

        // epilogue: cand = ||c||^2 - 2 x.c ; running min
        #pragma unroll
        for (int mi = 0; mi < 2; mi++)
            #pragma unroll
            for (int nj = 0; nj < 8; nj++) {
                int col = t * BN + warpN * 64 + nj * 8 + 2 * tig;
                float q0 = csq_s[col]     - 2.f * c[mi][nj][0];
                float q1 = csq_s[col + 1] - 2.f * c[mi][nj][1];
                float q2 = csq_s[col]     - 2.f * c[mi][nj][2];
                float q3 = csq_s[col + 1] - 2.f * c[mi][nj][3];
                rm[mi][0] = fminf(rm[mi][0], fminf(q0, q1));
                rm[mi][1] = fminf(rm[mi][1], fminf(q2, q3));
            }

        if (t + 1 < NT) { CP_WAIT0(); __syncthreads(); }
    }

    // ---- reduction: min across tig lanes, across warpN, then sqrt & sum ----
    float* minb = (float*)(smem + SMINB);
    #pragma unroll
    for (int mi = 0; mi < 2; mi++)
        #pragma unroll
        for (int h = 0; h < 2; h++) {
            float v = rm[mi][h];
            v = fminf(v, __shfl_xor_sync(0xffffffffu, v, 1));
            v = fminf(v, __shfl_xor_sync(0xffffffffu, v, 2));
            if (tig == 0)
                minb[(m0 + mi * 16 + g + 8 * h) * 2 + warpN] = v;
        }
    __syncthreads();
    if (tid < 128) {
        float m  = fminf(minb[2 * tid], minb[2 * tid + 1]);
        float xs = ((float*)(smem + SXSQ))[tid];
        float d  = sqrtf(fmaxf(xs + m, 0.f));
        #pragma unroll
        for (int off = 16; off; off >>= 1)
            d += __shfl_xor_sync(0xffffffffu, d, off);
        if (lane == 0) ((float*)(smem + SRED))[w] = d;
    }
    __syncthreads();
    if (tid == 0) {
        float* red = (float*)(smem + SRED);
        g_partials[blockIdx.x] = (red[0] + red[1]) + (red[2] + red[3]);
    }
}

// ---------------------------------------------------------------------------
// Kernel 2: deterministic tree reduce of 512 block partials -> scalar.
// ---------------------------------------------------------------------------
__global__ void finalize_kernel(float* __restrict__ out) {
    __shared__ float s[512];
    int tid = threadIdx.x;
    s[tid] = g_partials[tid];
    __syncthreads();
    #pragma unroll
    for (int off = 256; off; off >>= 1) {
        if (tid < off) s[tid] += s[tid + off];
        __syncthreads();
    }
    if (tid == 0) out[0] = s[0] * (ALPHA / (float)BATCH);
}

// ---------------------------------------------------------------------------
extern "C" void kernel_launch(void* const* d_in, const int* in_sizes, int n_in,
                              void* d_out, int out_size) {
    const float* emb;
    const float* cen;
    if (in_sizes[0] == BATCH * DIM) {
        emb = (const float*)d_in[0];
        cen = (const float*)d_in[1];
    } else {
        emb = (const float*)d_in[1];
        cen = (const float*)d_in[0];
    }
    float* out = (float*)d_out;

    cudaFuncSetAttribute(kmeans_main,
                         cudaFuncAttributeMaxDynamicSharedMemorySize, SMEM_TOTAL);

    prep_kernel<<<NUMC / 8, 256>>>(cen);
    kmeans_main<<<NBLOCKS, THREADS, SMEM_TOTAL>>>(emb);
    finalize_kernel<<<1, 512>>>(out);
}